// round 17
// baseline (speedup 1.0000x reference)
#include <cuda_runtime.h>
#include <cstddef>
#include <cstdint>

// ---------------------------------------------------------------------------
// KGAT forward, round 16.
//   Round-15 single-block scan (270us!) replaced by 3-phase chip-wide scan.
//   - COO -> CSR built on device each call (deterministic work, no allocs).
//   - SpMM: warp-per-row gather + register accumulate (no float atomics).
//   - Transform: register-tiled dual-GEMM, fused LeakyReLU + bi-sum + L2-norm.
// ---------------------------------------------------------------------------

#define NMAX   170000
#define NNZMAX 2720000
#define SCAN_CHUNK 4096          // elements per scan block (256 thr x 16)
#define MAX_PARTS  64            // ceil(170000/4096) = 42 <= 64

__device__ float g_side[(size_t)NMAX * 64];
__device__ float g_egoA[(size_t)NMAX * 64];
__device__ float g_egoB[(size_t)NMAX * 64];
__device__ int   g_rowptr[NMAX + 1];
__device__ int   g_cnt[NMAX];           // counts -> exclusive scan -> cursor
__device__ int   g_parts[MAX_PARTS + 1];
__device__ int2  g_edges[NNZMAX];       // (col, val-bits) grouped by row

// ---------------------------------------------------------------------------
// CSR build
// ---------------------------------------------------------------------------
__global__ void zeroi_kernel(int* __restrict__ p, int n) {
    int i = blockIdx.x * blockDim.x + threadIdx.x;
    if (i < n) p[i] = 0;
}

__global__ void hist_kernel(const int* __restrict__ rows, int* __restrict__ cnt,
                            int nnz) {
    int e = blockIdx.x * blockDim.x + threadIdx.x;
    if (e < nnz) atomicAdd(&cnt[rows[e]], 1);
}

// Phase 1: per-chunk reduction. 256 threads x 16 elements.
__global__ void __launch_bounds__(256)
scan_reduce_kernel(const int* __restrict__ cnt, int* __restrict__ parts, int n) {
    __shared__ int warp_sums[8];
    int tid  = threadIdx.x;
    int base = blockIdx.x * SCAN_CHUNK + tid * 16;
    int s = 0;
    #pragma unroll
    for (int j = 0; j < 16; j++) {
        int i = base + j;
        if (i < n) s += cnt[i];
    }
    #pragma unroll
    for (int d = 16; d > 0; d >>= 1) s += __shfl_xor_sync(0xffffffffu, s, d);
    if ((tid & 31) == 0) warp_sums[tid >> 5] = s;
    __syncthreads();
    if (tid == 0) {
        int t = 0;
        #pragma unroll
        for (int w = 0; w < 8; w++) t += warp_sums[w];
        parts[blockIdx.x] = t;
    }
}

// Phase 2: single-warp scan of <=64 partials -> exclusive; parts[np] = total.
__global__ void scan_parts_kernel(int* __restrict__ parts, int nparts) {
    int lane = threadIdx.x;                      // 32 threads
    int v0 = (lane < nparts) ? parts[lane] : 0;
    int v1 = (32 + lane < nparts) ? parts[32 + lane] : 0;
    int o0 = v0, o1 = v1;
    #pragma unroll
    for (int d = 1; d < 32; d <<= 1) {
        int t = __shfl_up_sync(0xffffffffu, v0, d);
        if (lane >= d) v0 += t;
    }
    int sum0 = __shfl_sync(0xffffffffu, v0, 31);
    #pragma unroll
    for (int d = 1; d < 32; d <<= 1) {
        int t = __shfl_up_sync(0xffffffffu, v1, d);
        if (lane >= d) v1 += t;
    }
    v1 += sum0;
    int total = __shfl_sync(0xffffffffu, v1, 31);
    if (lane < nparts)      parts[lane]      = v0 - o0;   // exclusive
    if (32 + lane < nparts) parts[32 + lane] = v1 - o1;
    if (lane == 0)          parts[nparts]    = total;
}

// Phase 3: per-chunk rescan with global offset. Writes rowptr + cursor.
__global__ void __launch_bounds__(256)
scan_chunk_kernel(int* __restrict__ cnt, const int* __restrict__ parts,
                  int* __restrict__ rowptr, int n, int nparts) {
    __shared__ int warp_sums[8];
    int tid  = threadIdx.x;
    int lane = tid & 31;
    int wrp  = tid >> 5;
    int base = blockIdx.x * SCAN_CHUNK + tid * 16;

    int v[16];
    int s = 0;
    #pragma unroll
    for (int j = 0; j < 16; j++) {
        int i = base + j;
        v[j] = (i < n) ? cnt[i] : 0;
        s += v[j];
    }
    // exclusive scan of per-thread sums across the block
    int inc = s;
    #pragma unroll
    for (int d = 1; d < 32; d <<= 1) {
        int t = __shfl_up_sync(0xffffffffu, inc, d);
        if (lane >= d) inc += t;
    }
    if (lane == 31) warp_sums[wrp] = inc;
    __syncthreads();
    int woff = 0;
    #pragma unroll
    for (int w = 0; w < 8; w++) woff += (w < wrp) ? warp_sums[w] : 0;
    int off = parts[blockIdx.x] + woff + (inc - s);   // global exclusive prefix

    #pragma unroll
    for (int j = 0; j < 16; j++) {
        int i = base + j;
        if (i < n) {
            rowptr[i] = off;
            cnt[i]    = off;    // permute cursor
        }
        off += v[j];
    }
    if (blockIdx.x == 0 && tid == 0) rowptr[n] = parts[nparts];
}

__global__ void permute_kernel(const int* __restrict__ rows,
                               const int* __restrict__ cols,
                               const float* __restrict__ vals,
                               int* __restrict__ cursor,
                               int2* __restrict__ edges, int nnz) {
    int e = blockIdx.x * blockDim.x + threadIdx.x;
    if (e >= nnz) return;
    int r = rows[e];
    int slot = atomicAdd(&cursor[r], 1);
    edges[slot] = make_int2(cols[e], __float_as_int(vals[e]));
}

// ---------------------------------------------------------------------------
// CSR SpMM: one warp per destination row, register accumulation, no atomics.
// ---------------------------------------------------------------------------
template <int DIN>
__global__ void __launch_bounds__(256)
spmm_csr_kernel(const int* __restrict__ rowptr, const int2* __restrict__ edges,
                const float* __restrict__ ego, float* __restrict__ side, int n) {
    int warp = (int)((blockIdx.x * blockDim.x + threadIdx.x) >> 5);
    int lane = threadIdx.x & 31;
    if (warp >= n) return;

    int beg = __ldg(&rowptr[warp]);
    int end = __ldg(&rowptr[warp + 1]);

    if constexpr (DIN == 64) {
        float ax = 0.f, ay = 0.f;
        int e = beg;
        for (; e + 2 <= end; e += 2) {
            int2 d0 = __ldg(&edges[e]);
            int2 d1 = __ldg(&edges[e + 1]);
            float2 x0 = __ldg((const float2*)(ego + (size_t)d0.x * 64) + lane);
            float2 x1 = __ldg((const float2*)(ego + (size_t)d1.x * 64) + lane);
            float v0 = __int_as_float(d0.y);
            float v1 = __int_as_float(d1.y);
            ax = fmaf(v0, x0.x, ax); ay = fmaf(v0, x0.y, ay);
            ax = fmaf(v1, x1.x, ax); ay = fmaf(v1, x1.y, ay);
        }
        if (e < end) {
            int2 d0 = __ldg(&edges[e]);
            float2 x0 = __ldg((const float2*)(ego + (size_t)d0.x * 64) + lane);
            float v0 = __int_as_float(d0.y);
            ax = fmaf(v0, x0.x, ax); ay = fmaf(v0, x0.y, ay);
        }
        float2 r; r.x = ax; r.y = ay;
        ((float2*)(side + (size_t)warp * 64))[lane] = r;
    } else {  // DIN == 32
        float a = 0.f;
        int e = beg;
        for (; e + 2 <= end; e += 2) {
            int2 d0 = __ldg(&edges[e]);
            int2 d1 = __ldg(&edges[e + 1]);
            float x0 = __ldg(ego + (size_t)d0.x * 32 + lane);
            float x1 = __ldg(ego + (size_t)d1.x * 32 + lane);
            a = fmaf(__int_as_float(d0.y), x0, a);
            a = fmaf(__int_as_float(d1.y), x1, a);
        }
        if (e < end) {
            int2 d0 = __ldg(&edges[e]);
            float x0 = __ldg(ego + (size_t)d0.x * 32 + lane);
            a = fmaf(__int_as_float(d0.y), x0, a);
        }
        side[(size_t)warp * 32 + lane] = a;
    }
}

// ---------------------------------------------------------------------------
// Copy raw embeddings into output columns [0, 64)
// ---------------------------------------------------------------------------
__global__ void copy_emb_kernel(const float4* __restrict__ emb,
                                float* __restrict__ out, int n) {
    int i = blockIdx.x * blockDim.x + threadIdx.x;
    if (i >= n * 16) return;
    int node = i >> 4;
    int c    = i & 15;
    float4 v = emb[(size_t)node * 16 + c];
    *reinterpret_cast<float4*>(&out[(size_t)node * 176 + c * 4]) = v;
}

// ---------------------------------------------------------------------------
// Register-tiled bi-interaction transform (unchanged from round 15).
// ---------------------------------------------------------------------------
union F4 { float4 v; float f[4]; };

template <int DIN, int DOUT, int OFF, int NT>
__global__ void __launch_bounds__(128)
transform_kernel(const float* __restrict__ ego,
                 const float* __restrict__ side,
                 const float* __restrict__ w1, const float* __restrict__ b1,
                 const float* __restrict__ w2, const float* __restrict__ b2,
                 float* __restrict__ ego_out,
                 float* __restrict__ out, int n) {
    constexpr int DINP = DIN + 4;
    constexpr int OT   = DOUT / 4;

    extern __shared__ float sm[];
    float* sSum  = sm;
    float* sPrd  = sSum + NT * DINP;
    float* sW1   = sPrd + NT * DINP;
    float* sW2   = sW1  + DIN * DOUT;
    float* sNorm = sW2  + DIN * DOUT;

    int tid   = threadIdx.x;
    int node0 = blockIdx.x * NT;

    for (int i = tid; i < DIN * DOUT; i += 128) {
        sW1[i] = __ldg(&w1[i]);
        sW2[i] = __ldg(&w2[i]);
    }
    for (int idx = tid; idx < NT * (DIN / 4); idx += 128) {
        int nd = idx / (DIN / 4);
        int kk = idx % (DIN / 4);
        float4 e = make_float4(0.f, 0.f, 0.f, 0.f);
        float4 s = e;
        if (node0 + nd < n) {
            e = *reinterpret_cast<const float4*>(ego  + (size_t)(node0 + nd) * DIN + kk * 4);
            s = *reinterpret_cast<const float4*>(side + (size_t)(node0 + nd) * DIN + kk * 4);
        }
        float4 su = make_float4(e.x + s.x, e.y + s.y, e.z + s.z, e.w + s.w);
        float4 pr = make_float4(e.x * s.x, e.y * s.y, e.z * s.z, e.w * s.w);
        *reinterpret_cast<float4*>(&sSum[nd * DINP + kk * 4]) = su;
        *reinterpret_cast<float4*>(&sPrd[nd * DINP + kk * 4]) = pr;
    }
    for (int i = tid; i < NT; i += 128) sNorm[i] = 0.f;
    __syncthreads();

    int ot  = tid % OT;
    int ntl = tid / OT;

    float b1a[4], b2a[4];
    #pragma unroll
    for (int j = 0; j < 4; j++) {
        b1a[j] = __ldg(&b1[ot * 4 + j]);
        b2a[j] = __ldg(&b2[ot * 4 + j]);
    }

    float acc1[8][4], acc2[8][4];
    #pragma unroll
    for (int i = 0; i < 8; i++)
        #pragma unroll
        for (int j = 0; j < 4; j++) { acc1[i][j] = b1a[j]; acc2[i][j] = b2a[j]; }

    for (int k4 = 0; k4 < DIN; k4 += 4) {
        F4 w1f[4], w2f[4];
        #pragma unroll
        for (int kk = 0; kk < 4; kk++) {
            w1f[kk].v = *reinterpret_cast<const float4*>(&sW1[(k4 + kk) * DOUT + ot * 4]);
            w2f[kk].v = *reinterpret_cast<const float4*>(&sW2[(k4 + kk) * DOUT + ot * 4]);
        }
        #pragma unroll
        for (int i = 0; i < 8; i++) {
            F4 su, pr;
            su.v = *reinterpret_cast<const float4*>(&sSum[(ntl * 8 + i) * DINP + k4]);
            pr.v = *reinterpret_cast<const float4*>(&sPrd[(ntl * 8 + i) * DINP + k4]);
            #pragma unroll
            for (int kk = 0; kk < 4; kk++) {
                float sv = su.f[kk], pv = pr.f[kk];
                #pragma unroll
                for (int j = 0; j < 4; j++) {
                    acc1[i][j] = fmaf(sv, w1f[kk].f[j], acc1[i][j]);
                    acc2[i][j] = fmaf(pv, w2f[kk].f[j], acc2[i][j]);
                }
            }
        }
    }

    #pragma unroll
    for (int i = 0; i < 8; i++) {
        float ss = 0.f;
        #pragma unroll
        for (int j = 0; j < 4; j++) {
            float x1 = acc1[i][j]; x1 = (x1 >= 0.f) ? x1 : 0.01f * x1;
            float x2 = acc2[i][j]; x2 = (x2 >= 0.f) ? x2 : 0.01f * x2;
            float v = x1 + x2;
            acc1[i][j] = v;
            ss = fmaf(v, v, ss);
        }
        atomicAdd(&sNorm[ntl * 8 + i], ss);
    }
    __syncthreads();

    #pragma unroll
    for (int i = 0; i < 8; i++) {
        int nd   = ntl * 8 + i;
        int node = node0 + nd;
        if (node >= n) continue;
        float sc = 1.0f / fmaxf(sqrtf(sNorm[nd]), 1e-12f);
        float4 ve = make_float4(acc1[i][0], acc1[i][1], acc1[i][2], acc1[i][3]);
        float4 vo = make_float4(ve.x * sc, ve.y * sc, ve.z * sc, ve.w * sc);
        *reinterpret_cast<float4*>(&ego_out[(size_t)node * DOUT + ot * 4]) = ve;
        *reinterpret_cast<float4*>(&out[(size_t)node * 176 + OFF + ot * 4]) = vo;
    }
}

// ---------------------------------------------------------------------------
// Launch
// ---------------------------------------------------------------------------
extern "C" void kernel_launch(void* const* d_in, const int* in_sizes, int n_in,
                              void* d_out, int out_size) {
    const float* emb    = (const float*)d_in[0];
    const float* a_vals = (const float*)d_in[1];
    const float* w1_0 = (const float*)d_in[2];
    const float* b1_0 = (const float*)d_in[3];
    const float* w2_0 = (const float*)d_in[4];
    const float* b2_0 = (const float*)d_in[5];
    const float* w1_1 = (const float*)d_in[6];
    const float* b1_1 = (const float*)d_in[7];
    const float* w2_1 = (const float*)d_in[8];
    const float* b2_1 = (const float*)d_in[9];
    const float* w1_2 = (const float*)d_in[10];
    const float* b1_2 = (const float*)d_in[11];
    const float* w2_2 = (const float*)d_in[12];
    const float* b2_2 = (const float*)d_in[13];
    const int* a_rows = (const int*)d_in[14];
    const int* a_cols = (const int*)d_in[15];

    const int nnz = in_sizes[1];
    const int n   = in_sizes[0] / 64;
    float* out = (float*)d_out;

    float *side = nullptr, *egoA = nullptr, *egoB = nullptr;
    int *rowptr = nullptr, *cnt = nullptr, *parts = nullptr;
    int2 *edges = nullptr;
    cudaGetSymbolAddress((void**)&side,   g_side);
    cudaGetSymbolAddress((void**)&egoA,   g_egoA);
    cudaGetSymbolAddress((void**)&egoB,   g_egoB);
    cudaGetSymbolAddress((void**)&rowptr, g_rowptr);
    cudaGetSymbolAddress((void**)&cnt,    g_cnt);
    cudaGetSymbolAddress((void**)&parts,  g_parts);
    cudaGetSymbolAddress((void**)&edges,  g_edges);

    const int TB = 256;

    constexpr int SM0 = (2 * 64  * 68 + 2 * 64 * 64 + 64)  * 4;
    constexpr int SM1 = (2 * 128 * 68 + 2 * 64 * 32 + 128) * 4;
    constexpr int SM2 = (2 * 256 * 36 + 2 * 32 * 16 + 256) * 4;
    cudaFuncSetAttribute((const void*)transform_kernel<64, 64, 64, 64>,
                         cudaFuncAttributeMaxDynamicSharedMemorySize, SM0);
    cudaFuncSetAttribute((const void*)transform_kernel<64, 32, 128, 128>,
                         cudaFuncAttributeMaxDynamicSharedMemorySize, SM1);
    cudaFuncSetAttribute((const void*)transform_kernel<32, 16, 160, 256>,
                         cudaFuncAttributeMaxDynamicSharedMemorySize, SM2);

    // out[:, 0:64] = raw embeddings
    copy_emb_kernel<<<(n * 16 + TB - 1) / TB, TB>>>((const float4*)emb, out, n);

    // ---- CSR build ----
    const int nparts = (n + SCAN_CHUNK - 1) / SCAN_CHUNK;   // 42
    zeroi_kernel<<<(n + TB - 1) / TB, TB>>>(cnt, n);
    hist_kernel<<<(nnz + TB - 1) / TB, TB>>>(a_rows, cnt, nnz);
    scan_reduce_kernel<<<nparts, 256>>>(cnt, parts, n);
    scan_parts_kernel<<<1, 32>>>(parts, nparts);
    scan_chunk_kernel<<<nparts, 256>>>(cnt, parts, rowptr, n, nparts);
    permute_kernel<<<(nnz + TB - 1) / TB, TB>>>(a_rows, a_cols, a_vals, cnt,
                                                edges, nnz);

    const int spmm_blocks = (n + 7) / 8;

    // ---- layer 0: 64 -> 64, cols [64,128) ----
    spmm_csr_kernel<64><<<spmm_blocks, TB>>>(rowptr, edges, emb, side, n);
    transform_kernel<64, 64, 64, 64><<<(n + 63) / 64, 128, SM0>>>(
        emb, side, w1_0, b1_0, w2_0, b2_0, egoA, out, n);

    // ---- layer 1: 64 -> 32, cols [128,160) ----
    spmm_csr_kernel<64><<<spmm_blocks, TB>>>(rowptr, edges, egoA, side, n);
    transform_kernel<64, 32, 128, 128><<<(n + 127) / 128, 128, SM1>>>(
        egoA, side, w1_1, b1_1, w2_1, b2_1, egoB, out, n);

    // ---- layer 2: 32 -> 16, cols [160,176) ----
    spmm_csr_kernel<32><<<spmm_blocks, TB>>>(rowptr, edges, egoB, side, n);
    transform_kernel<32, 16, 160, 256><<<(n + 255) / 256, 128, SM2>>>(
        egoB, side, w1_2, b1_2, w2_2, b2_2, egoA, out, n);
}